// round 1
// baseline (speedup 1.0000x reference)
#include <cuda_runtime.h>
#include <math.h>

#define BT   2048     // B*T
#define DM   1024     // d_model
#define NH   16
#define DKV  64
#define DFF  2736

// ---------------- scratch (static device globals; no allocation) ----------------
__device__ float g_h [BT*DM];
__device__ float g_q [BT*DM];
__device__ float g_k [BT*DM];
__device__ float g_v [BT*DM];
__device__ float g_a [BT*DM];
__device__ float g_o [BT*DM];
__device__ float g_x1[BT*DM];
__device__ float g_f1[BT*DFF];
__device__ float g_f2[BT*DFF];

// ---------------- RMSNorm: one block per row of 1024 ----------------
__global__ void rmsnorm_kernel(const float* __restrict__ x,
                               const float* __restrict__ g,
                               float* __restrict__ out)
{
    const int row = blockIdx.x;
    const float4* xr = (const float4*)(x + (size_t)row * DM);
    const float4* gr = (const float4*)g;
    float4 v = xr[threadIdx.x];
    float s = v.x*v.x + v.y*v.y + v.z*v.z + v.w*v.w;
    #pragma unroll
    for (int o = 16; o > 0; o >>= 1) s += __shfl_xor_sync(0xFFFFFFFFu, s, o);
    __shared__ float red[8];
    if ((threadIdx.x & 31) == 0) red[threadIdx.x >> 5] = s;
    __syncthreads();
    float tot = red[0]+red[1]+red[2]+red[3]+red[4]+red[5]+red[6]+red[7];
    float sc = rsqrtf(tot * (1.0f/(float)DM) + 1e-6f);
    float4 gv = gr[threadIdx.x];
    float4 o4;
    o4.x = v.x * sc * gv.x;
    o4.y = v.y * sc * gv.y;
    o4.z = v.z * sc * gv.z;
    o4.w = v.w * sc * gv.w;
    ((float4*)(out + (size_t)row * DM))[threadIdx.x] = o4;
}

// ---------------- q/k L2-norm per head + sigmoid(alpha), in place ----------------
// one block per token, 256 threads = 8 warps; warp w handles heads w and w+8
__global__ void qknorm_kernel(float* __restrict__ q,
                              float* __restrict__ k,
                              float* __restrict__ a)
{
    const int row  = blockIdx.x;
    const int lane = threadIdx.x & 31;
    const int w    = threadIdx.x >> 5;
    float2* qr = (float2*)(q + (size_t)row * DM);
    float2* kr = (float2*)(k + (size_t)row * DM);

    #pragma unroll
    for (int it = 0; it < 2; ++it) {
        const int h = w + it * 8;
        // q
        {
            float2 v = qr[h*32 + lane];
            float s = v.x*v.x + v.y*v.y;
            #pragma unroll
            for (int o = 16; o > 0; o >>= 1) s += __shfl_xor_sync(0xFFFFFFFFu, s, o);
            float inv = 1.0f / fmaxf(sqrtf(s), 1e-12f);
            v.x *= inv; v.y *= inv;
            qr[h*32 + lane] = v;
        }
        // k
        {
            float2 v = kr[h*32 + lane];
            float s = v.x*v.x + v.y*v.y;
            #pragma unroll
            for (int o = 16; o > 0; o >>= 1) s += __shfl_xor_sync(0xFFFFFFFFu, s, o);
            float inv = 1.0f / fmaxf(sqrtf(s), 1e-12f);
            v.x *= inv; v.y *= inv;
            kr[h*32 + lane] = v;
        }
    }
    // alpha = sigmoid
    float* ar = a + (size_t)row * DM;
    for (int i = threadIdx.x; i < DM; i += 256) {
        float z = ar[i];
        ar[i] = 1.0f / (1.0f + __expf(-z));
    }
}

// ---------------- sequential GLA scan ----------------
// grid = B*H = 32 blocks, 64 threads; thread owns one v-column (S[:,v] in regs)
__global__ void scan_kernel(const float* __restrict__ q,
                            const float* __restrict__ k,
                            const float* __restrict__ v,
                            const float* __restrict__ a,
                            float* __restrict__ o)
{
    const int b  = blockIdx.x >> 4;
    const int h  = blockIdx.x & 15;
    const int vi = threadIdx.x;           // 0..63
    const size_t base = (size_t)b * 1024 * DM + h * DKV;
    const float* qb = q + base;
    const float* kb = k + base;
    const float* vb = v + base;
    const float* ab = a + base;
    float*       ob = o + base;

    __shared__ float sh[2][4][DKV];       // [buf][a,k,q,v]

    float S[DKV];
    #pragma unroll
    for (int d = 0; d < DKV; ++d) S[d] = 0.0f;

    // preload t=0 into buffer 0
    sh[0][0][vi] = ab[vi];
    sh[0][1][vi] = kb[vi];
    sh[0][2][vi] = qb[vi];
    sh[0][3][vi] = vb[vi];
    __syncthreads();

    for (int t = 0; t < 1024; ++t) {
        const int cur = t & 1;
        if (t + 1 < 1024) {
            const size_t off = (size_t)(t + 1) * DM;
            sh[cur^1][0][vi] = ab[off + vi];
            sh[cur^1][1][vi] = kb[off + vi];
            sh[cur^1][2][vi] = qb[off + vi];
            sh[cur^1][3][vi] = vb[off + vi];
        }
        const float vv = sh[cur][3][vi];
        float acc = 0.0f;
        #pragma unroll
        for (int d = 0; d < DKV; ++d) {
            S[d] = fmaf(sh[cur][0][d], S[d], sh[cur][1][d] * vv);
            acc  = fmaf(sh[cur][2][d], S[d], acc);
        }
        ob[(size_t)t * DM + vi] = acc;
        __syncthreads();
    }
}

// ---------------- SGEMM: C[z] = A @ B[z] (+R), A[M,K], B[K,N] row-major ----------
// 64x128 block tile, BK=16, 128 threads, 8x8 per thread
struct Ptrs4 {
    const float* B[4];
    float*       C[4];
};

template<bool HAS_RES>
__global__ __launch_bounds__(128)
void sgemm_kernel(const float* __restrict__ A, Ptrs4 p,
                  const float* __restrict__ R,
                  int M, int N, int K)
{
    const float* __restrict__ B = p.B[blockIdx.z];
    float* __restrict__       C = p.C[blockIdx.z];

    __shared__ float As[16][68];   // padded: stride 68 avoids STS bank conflicts
    __shared__ float Bs[16][128];

    const int tid = threadIdx.x;
    const int bm = blockIdx.y * 64;
    const int bn = blockIdx.x * 128;
    const int tx = tid & 15;
    const int ty = tid >> 4;

    const int aRow = tid >> 2;           // 0..31
    const int aCol = (tid & 3) * 4;      // 0,4,8,12
    const int bRow = tid >> 5;           // 0..3
    const int bCol = (tid & 31) * 4;     // 0..124
    const bool bOk = (bn + bCol) < N;    // N % 4 == 0 so float4 safe when true

    float acc[64];
    #pragma unroll
    for (int i = 0; i < 64; ++i) acc[i] = 0.0f;

    const float* Ap = A + (size_t)(bm + aRow) * K + aCol;
    const float* Bp = B + (size_t)bRow * N + bn + bCol;

    for (int k0 = 0; k0 < K; k0 += 16) {
        #pragma unroll
        for (int i = 0; i < 2; ++i) {
            float4 va = *(const float4*)(Ap + (size_t)i * 32 * K + k0);
            As[aCol+0][aRow + i*32] = va.x;
            As[aCol+1][aRow + i*32] = va.y;
            As[aCol+2][aRow + i*32] = va.z;
            As[aCol+3][aRow + i*32] = va.w;
        }
        #pragma unroll
        for (int i = 0; i < 4; ++i) {
            float4 vb = make_float4(0.f, 0.f, 0.f, 0.f);
            if (bOk) vb = *(const float4*)(Bp + (size_t)(k0 + i*4) * N);
            *(float4*)&Bs[bRow + i*4][bCol] = vb;
        }
        __syncthreads();

        #pragma unroll
        for (int kk = 0; kk < 16; ++kk) {
            float ar[8], br[8];
            #pragma unroll
            for (int i = 0; i < 8; ++i) ar[i] = As[kk][ty*8 + i];
            #pragma unroll
            for (int j = 0; j < 8; ++j) br[j] = Bs[kk][tx*8 + j];
            #pragma unroll
            for (int i = 0; i < 8; ++i)
                #pragma unroll
                for (int j = 0; j < 8; ++j)
                    acc[i*8 + j] = fmaf(ar[i], br[j], acc[i*8 + j]);
        }
        __syncthreads();
    }

    #pragma unroll
    for (int i = 0; i < 8; ++i) {
        const int row = bm + ty*8 + i;
        #pragma unroll
        for (int jj = 0; jj < 2; ++jj) {
            const int col = bn + tx*8 + jj*4;
            if (col < N) {
                float4 o;
                o.x = acc[i*8 + jj*4 + 0];
                o.y = acc[i*8 + jj*4 + 1];
                o.z = acc[i*8 + jj*4 + 2];
                o.w = acc[i*8 + jj*4 + 3];
                if (HAS_RES) {
                    float4 r = *(const float4*)(R + (size_t)row * N + col);
                    o.x += r.x; o.y += r.y; o.z += r.z; o.w += r.w;
                }
                *(float4*)(C + (size_t)row * N + col) = o;
            }
        }
    }
}

// ---------------- SwiGLU: f1 = silu(f1) * f2 ----------------
__global__ void swiglu_kernel(float* __restrict__ f1, const float* __restrict__ f2, int n4)
{
    int i = blockIdx.x * blockDim.x + threadIdx.x;
    if (i < n4) {
        float4 a = ((const float4*)f1)[i];
        float4 b = ((const float4*)f2)[i];
        a.x = a.x / (1.0f + __expf(-a.x)) * b.x;
        a.y = a.y / (1.0f + __expf(-a.y)) * b.y;
        a.z = a.z / (1.0f + __expf(-a.z)) * b.z;
        a.w = a.w / (1.0f + __expf(-a.w)) * b.w;
        ((float4*)f1)[i] = a;
    }
}

// ---------------- host launcher ----------------
extern "C" void kernel_launch(void* const* d_in, const int* in_sizes, int n_in,
                              void* d_out, int out_size)
{
    const float* x     = (const float*)d_in[0];
    const float* Wq    = (const float*)d_in[1];
    const float* Wk    = (const float*)d_in[2];
    const float* Wv    = (const float*)d_in[3];
    const float* Wg    = (const float*)d_in[4];
    const float* Wo    = (const float*)d_in[5];
    const float* w1    = (const float*)d_in[6];
    const float* w2    = (const float*)d_in[7];
    const float* w3    = (const float*)d_in[8];
    const float* gat   = (const float*)d_in[9];
    const float* gff   = (const float*)d_in[10];
    float* out = (float*)d_out;

    float *ph, *pq, *pk, *pv, *pa, *po, *px1, *pf1, *pf2;
    cudaGetSymbolAddress((void**)&ph,  g_h);
    cudaGetSymbolAddress((void**)&pq,  g_q);
    cudaGetSymbolAddress((void**)&pk,  g_k);
    cudaGetSymbolAddress((void**)&pv,  g_v);
    cudaGetSymbolAddress((void**)&pa,  g_a);
    cudaGetSymbolAddress((void**)&po,  g_o);
    cudaGetSymbolAddress((void**)&px1, g_x1);
    cudaGetSymbolAddress((void**)&pf1, g_f1);
    cudaGetSymbolAddress((void**)&pf2, g_f2);

    // 1) h = rmsnorm(x, g_attn)
    rmsnorm_kernel<<<BT, 256>>>(x, gat, ph);

    // 2) q,k,v,alpha raw = h @ {Wq,Wk,Wv,Wg}   (batched over z)
    {
        Ptrs4 p;
        p.B[0] = Wq; p.B[1] = Wk; p.B[2] = Wv; p.B[3] = Wg;
        p.C[0] = pq; p.C[1] = pk; p.C[2] = pv; p.C[3] = pa;
        dim3 grid(DM/128, BT/64, 4);
        sgemm_kernel<false><<<grid, 128>>>(ph, p, nullptr, BT, DM, DM);
    }

    // 3) l2norm(q), l2norm(k), sigmoid(alpha) in place
    qknorm_kernel<<<BT, 256>>>(pq, pk, pa);

    // 4) gated linear attention scan -> o
    scan_kernel<<<32, 64>>>(pq, pk, pv, pa, po);

    // 5) x1 = x + o @ Wo
    {
        Ptrs4 p;
        p.B[0] = Wo; p.C[0] = px1;
        for (int i = 1; i < 4; ++i) { p.B[i] = Wo; p.C[i] = px1; }
        dim3 grid(DM/128, BT/64, 1);
        sgemm_kernel<true><<<grid, 128>>>(po, p, x, BT, DM, DM);
    }

    // 6) h = rmsnorm(x1, g_ffn)
    rmsnorm_kernel<<<BT, 256>>>(px1, gff, ph);

    // 7) f1 = h @ w1 ; f2 = h @ w2   (batched over z)
    {
        Ptrs4 p;
        p.B[0] = w1; p.B[1] = w2; p.B[2] = w1; p.B[3] = w1;
        p.C[0] = pf1; p.C[1] = pf2; p.C[2] = pf1; p.C[3] = pf1;
        dim3 grid((DFF + 127)/128, BT/64, 2);
        sgemm_kernel<false><<<grid, 128>>>(ph, p, nullptr, BT, DFF, DM);
    }

    // 8) f1 = silu(f1) * f2
    {
        int n4 = (BT * DFF) / 4;
        swiglu_kernel<<<(n4 + 255)/256, 256>>>(pf1, pf2, n4);
    }

    // 9) out = x1 + f1 @ w3
    {
        Ptrs4 p;
        p.B[0] = w3; p.C[0] = out;
        for (int i = 1; i < 4; ++i) { p.B[i] = w3; p.C[i] = out; }
        dim3 grid(DM/128, BT/64, 1);
        sgemm_kernel<true><<<grid, 128>>>(pf1, p, px1, BT, DM, DFF);
    }
}

// round 3
// speedup vs baseline: 1.2991x; 1.2991x over previous
#include <cuda_runtime.h>
#include <math.h>

#define BT   2048     // B*T
#define DM   1024     // d_model
#define NH   16
#define DKV  64
#define DFF  2736
#define NC   16       // chunks per sequence (T=1024 / 64)
#define CS   64       // chunk size
#define NBHC 512      // B*H*NC = 2*16*16
#define PAD  68       // smem row stride (floats): 16B-aligned + bank skew

// ---------------- scratch (static device globals; no allocation) ----------------
__device__ float g_h [BT*DM];
__device__ float g_q [BT*DM];
__device__ float g_k [BT*DM];
__device__ float g_v [BT*DM];
__device__ float g_a [BT*DM];
__device__ float g_o [BT*DM];
__device__ float g_x1[BT*DM];
__device__ float g_f1[BT*DFF];
__device__ float g_f2[BT*DFF];
__device__ float g_P [NBHC*4096];   // per-chunk summary [dk,dv]
__device__ float g_Ss[NBHC*4096];   // state BEFORE each chunk [dk,dv]
__device__ float g_Ae[NBHC*64];     // per-chunk full gate product per dk-dim

// ---------------- RMSNorm: one block per row of 1024 ----------------
__global__ void rmsnorm_kernel(const float* __restrict__ x,
                               const float* __restrict__ g,
                               float* __restrict__ out)
{
    const int row = blockIdx.x;
    const float4* xr = (const float4*)(x + (size_t)row * DM);
    const float4* gr = (const float4*)g;
    float4 v = xr[threadIdx.x];
    float s = v.x*v.x + v.y*v.y + v.z*v.z + v.w*v.w;
    #pragma unroll
    for (int o = 16; o > 0; o >>= 1) s += __shfl_xor_sync(0xFFFFFFFFu, s, o);
    __shared__ float red[8];
    if ((threadIdx.x & 31) == 0) red[threadIdx.x >> 5] = s;
    __syncthreads();
    float tot = red[0]+red[1]+red[2]+red[3]+red[4]+red[5]+red[6]+red[7];
    float sc = rsqrtf(tot * (1.0f/(float)DM) + 1e-6f);
    float4 gv = gr[threadIdx.x];
    float4 o4;
    o4.x = v.x * sc * gv.x;
    o4.y = v.y * sc * gv.y;
    o4.z = v.z * sc * gv.z;
    o4.w = v.w * sc * gv.w;
    ((float4*)(out + (size_t)row * DM))[threadIdx.x] = o4;
}

// ---------------- q/k L2-norm per head + LOG-SIGMOID(gate), in place ----------------
__global__ void qknorm_kernel(float* __restrict__ q,
                              float* __restrict__ k,
                              float* __restrict__ a)
{
    const int row  = blockIdx.x;
    const int lane = threadIdx.x & 31;
    const int w    = threadIdx.x >> 5;
    float2* qr = (float2*)(q + (size_t)row * DM);
    float2* kr = (float2*)(k + (size_t)row * DM);

    #pragma unroll
    for (int it = 0; it < 2; ++it) {
        const int h = w + it * 8;
        {
            float2 v = qr[h*32 + lane];
            float s = v.x*v.x + v.y*v.y;
            #pragma unroll
            for (int o = 16; o > 0; o >>= 1) s += __shfl_xor_sync(0xFFFFFFFFu, s, o);
            float inv = 1.0f / fmaxf(sqrtf(s), 1e-12f);
            v.x *= inv; v.y *= inv;
            qr[h*32 + lane] = v;
        }
        {
            float2 v = kr[h*32 + lane];
            float s = v.x*v.x + v.y*v.y;
            #pragma unroll
            for (int o = 16; o > 0; o >>= 1) s += __shfl_xor_sync(0xFFFFFFFFu, s, o);
            float inv = 1.0f / fmaxf(sqrtf(s), 1e-12f);
            v.x *= inv; v.y *= inv;
            kr[h*32 + lane] = v;
        }
    }
    // a <- log(sigmoid(a))  (stable both tails)
    float* ar = a + (size_t)row * DM;
    for (int i = threadIdx.x; i < DM; i += 256) {
        float z = ar[i];
        float l = (z >= 0.0f) ? -log1pf(__expf(-z)) : (z - log1pf(__expf(z)));
        ar[i] = l;
    }
}

// ---------------- Kernel 1: per-chunk cumprods, q~/k~, summary P ----------------
// grid = NBHC (bh*16 + c), 256 threads
__global__ __launch_bounds__(256) void chunk_summary_kernel(
    float* __restrict__ q, float* __restrict__ k,
    const float* __restrict__ v, const float* __restrict__ la,
    float* __restrict__ P, float* __restrict__ Ae)
{
    __shared__ float Ash[CS][64];
    __shared__ float Ks [CS][64];
    __shared__ float Vs [CS][64];

    const int bhc = blockIdx.x;
    const int bh  = bhc >> 4, c = bhc & 15;
    const int b   = bh >> 4,  h = bh & 15;
    const int tid = threadIdx.x;
    const int d   = tid & 63, j0 = tid >> 6;
    const size_t base = ((size_t)(b*1024 + c*CS)) * DM + h*64;

    #pragma unroll
    for (int i = 0; i < 16; ++i) {
        const int j = j0 + 4*i;
        Ash[j][d] = la[base + (size_t)j*DM + d];
    }
    __syncthreads();

    if (tid < 64) {                      // per-dim inclusive cumprod via log-cumsum
        float cum = 0.0f, Aj = 1.0f;
        #pragma unroll
        for (int j = 0; j < CS; ++j) {
            cum += Ash[j][tid];
            Aj = __expf(cum);
            Ash[j][tid] = Aj;
        }
        Ae[(size_t)bhc*64 + tid] = Aj;
    }
    __syncthreads();

    #pragma unroll
    for (int i = 0; i < 16; ++i) {
        const int j = j0 + 4*i;
        const size_t off = base + (size_t)j*DM + d;
        const float A = Ash[j][d];
        q[off] = q[off] * A;                       // q~ = q * A
        const float kv = __fdividef(k[off], A);    // k~ = k / A
        k[off] = kv;
        Ks[j][d] = kv;
        Vs[j][d] = v[off];
    }
    __syncthreads();

    // P[d][e] = Aend_d * sum_i Ks[i][d]*Vs[i][e]   (4x4 register tile)
    const int dr = (tid >> 4) << 2;
    const int ec = (tid & 15) << 2;
    float acc[4][4];
    #pragma unroll
    for (int i = 0; i < 4; ++i)
        #pragma unroll
        for (int j = 0; j < 4; ++j) acc[i][j] = 0.0f;

    #pragma unroll 4
    for (int i2 = 0; i2 < CS; ++i2) {
        float kk[4], vv[4];
        *(float4*)kk = *(const float4*)&Ks[i2][dr];
        *(float4*)vv = *(const float4*)&Vs[i2][ec];
        #pragma unroll
        for (int i = 0; i < 4; ++i)
            #pragma unroll
            for (int j = 0; j < 4; ++j)
                acc[i][j] = fmaf(kk[i], vv[j], acc[i][j]);
    }

    float* Pp = P + (size_t)bhc * 4096;
    #pragma unroll
    for (int ii = 0; ii < 4; ++ii) {
        const float aend = Ash[CS-1][dr+ii];
        float4 o4;
        o4.x = acc[ii][0]*aend; o4.y = acc[ii][1]*aend;
        o4.z = acc[ii][2]*aend; o4.w = acc[ii][3]*aend;
        *(float4*)&Pp[(dr+ii)*64 + ec] = o4;
    }
}

// ---------------- Kernel 2: chunk-level state recurrence (16 steps) ----------------
// grid = 32 (b*h), 256 threads, each thread owns 16 elements of S[64][64]
__global__ __launch_bounds__(256) void chunk_state_kernel(
    const float* __restrict__ P, const float* __restrict__ Ae,
    float* __restrict__ S)
{
    const int bh  = blockIdx.x;
    const int tid = threadIdx.x;
    const int e   = tid & 63;
    const int d0  = tid >> 6;
    __shared__ float sae[64];

    float s[16];
    #pragma unroll
    for (int i = 0; i < 16; ++i) s[i] = 0.0f;

    for (int c = 0; c < NC; ++c) {
        const size_t idx = (size_t)bh*NC + c;
        if (tid < 64) sae[tid] = Ae[idx*64 + tid];
        __syncthreads();
        const float* Pc = P + idx*4096;
        float*       Sc = S + idx*4096;
        #pragma unroll
        for (int i = 0; i < 16; ++i) {
            const int d = d0 + 4*i;
            Sc[d*64 + e] = s[i];                       // state BEFORE chunk c
            s[i] = fmaf(sae[d], s[i], Pc[d*64 + e]);   // advance
        }
        __syncthreads();
    }
}

// ---------------- Kernel 3: intra-chunk outputs ----------------
// o_j = S0^T q~_j + sum_{i<=j} (q~_j . k~_i) v_i
// grid = NBHC, 256 threads, dynamic smem 4 * 64*PAD floats
__global__ __launch_bounds__(256) void chunk_output_kernel(
    const float* __restrict__ q, const float* __restrict__ k,
    const float* __restrict__ v, const float* __restrict__ S,
    float* __restrict__ o)
{
    extern __shared__ float sm3[];
    float (*Qs)[PAD] = (float(*)[PAD])(sm3);
    float (*KT)[PAD] = (float(*)[PAD])(sm3 + 64*PAD);
    float (*Bs)[PAD] = (float(*)[PAD])(sm3 + 2*64*PAD);
    float (*Sc)[PAD] = (float(*)[PAD])(sm3 + 3*64*PAD);

    const int bhc = blockIdx.x;
    const int bh  = bhc >> 4, c = bhc & 15;
    const int b   = bh >> 4,  h = bh & 15;
    const int tid = threadIdx.x;
    const int d   = tid & 63, j0 = tid >> 6;
    const size_t base = ((size_t)(b*1024 + c*CS)) * DM + h*64;
    const float* Sb = S + (size_t)bhc * 4096;

    #pragma unroll
    for (int i = 0; i < 16; ++i) {
        const int j = j0 + 4*i;
        Qs[j][d] = q[base + (size_t)j*DM + d];
        KT[d][j] = k[base + (size_t)j*DM + d];
        Bs[j][d] = Sb[j*64 + d];        // S0: row=dk, col=dv
    }
    __syncthreads();

    const int tr = (tid >> 4) << 2;     // output rows (tokens)
    const int tc = (tid & 15) << 2;     // output cols

    float acc[4][4], sca[4][4];
    #pragma unroll
    for (int i = 0; i < 4; ++i)
        #pragma unroll
        for (int j = 0; j < 4; ++j) { acc[i][j] = 0.0f; sca[i][j] = 0.0f; }

    // fused: O_part = Qs @ S0  and  scores = Qs @ KT
    #pragma unroll 4
    for (int dd = 0; dd < 64; ++dd) {
        float bv[4], kv[4], av[4];
        *(float4*)bv = *(const float4*)&Bs[dd][tc];
        *(float4*)kv = *(const float4*)&KT[dd][tc];
        #pragma unroll
        for (int i = 0; i < 4; ++i) av[i] = Qs[tr+i][dd];
        #pragma unroll
        for (int i = 0; i < 4; ++i)
            #pragma unroll
            for (int j = 0; j < 4; ++j) {
                acc[i][j] = fmaf(av[i], bv[j], acc[i][j]);
                sca[i][j] = fmaf(av[i], kv[j], sca[i][j]);
            }
    }

    // causal mask, stage scores to shared
    #pragma unroll
    for (int i = 0; i < 4; ++i)
        #pragma unroll
        for (int j = 0; j < 4; ++j)
            Sc[tr+i][tc+j] = ((tc+j) <= (tr+i)) ? sca[i][j] : 0.0f;
    __syncthreads();

    // overwrite Bs with V
    #pragma unroll
    for (int i = 0; i < 16; ++i) {
        const int j = j0 + 4*i;
        Bs[j][d] = v[base + (size_t)j*DM + d];
    }
    __syncthreads();

    // O += scores @ V
    #pragma unroll 4
    for (int dd = 0; dd < 64; ++dd) {
        float bv[4], av[4];
        *(float4*)bv = *(const float4*)&Bs[dd][tc];
        #pragma unroll
        for (int i = 0; i < 4; ++i) av[i] = Sc[tr+i][dd];
        #pragma unroll
        for (int i = 0; i < 4; ++i)
            #pragma unroll
            for (int j = 0; j < 4; ++j)
                acc[i][j] = fmaf(av[i], bv[j], acc[i][j]);
    }

    #pragma unroll
    for (int i = 0; i < 4; ++i) {
        float4 o4;
        o4.x = acc[i][0]; o4.y = acc[i][1]; o4.z = acc[i][2]; o4.w = acc[i][3];
        *(float4*)&o[base + (size_t)(tr+i)*DM + tc] = o4;
    }
}

// ---------------- SGEMM: C[z] = A @ B[z] (+R), A[M,K], B[K,N] row-major ----------
struct Ptrs4 {
    const float* B[4];
    float*       C[4];
};

template<bool HAS_RES>
__global__ __launch_bounds__(128)
void sgemm_kernel(const float* __restrict__ A, Ptrs4 p,
                  const float* __restrict__ R,
                  int M, int N, int K)
{
    const float* __restrict__ B = p.B[blockIdx.z];
    float* __restrict__       C = p.C[blockIdx.z];

    __shared__ float As[16][68];
    __shared__ float Bs[16][128];

    const int tid = threadIdx.x;
    const int bm = blockIdx.y * 64;
    const int bn = blockIdx.x * 128;
    const int tx = tid & 15;
    const int ty = tid >> 4;

    const int aRow = tid >> 2;
    const int aCol = (tid & 3) * 4;
    const int bRow = tid >> 5;
    const int bCol = (tid & 31) * 4;
    const bool bOk = (bn + bCol) < N;

    float acc[64];
    #pragma unroll
    for (int i = 0; i < 64; ++i) acc[i] = 0.0f;

    const float* Ap = A + (size_t)(bm + aRow) * K + aCol;
    const float* Bp = B + (size_t)bRow * N + bn + bCol;

    for (int k0 = 0; k0 < K; k0 += 16) {
        #pragma unroll
        for (int i = 0; i < 2; ++i) {
            float4 va = *(const float4*)(Ap + (size_t)i * 32 * K + k0);
            As[aCol+0][aRow + i*32] = va.x;
            As[aCol+1][aRow + i*32] = va.y;
            As[aCol+2][aRow + i*32] = va.z;
            As[aCol+3][aRow + i*32] = va.w;
        }
        #pragma unroll
        for (int i = 0; i < 4; ++i) {
            float4 vb = make_float4(0.f, 0.f, 0.f, 0.f);
            if (bOk) vb = *(const float4*)(Bp + (size_t)(k0 + i*4) * N);
            *(float4*)&Bs[bRow + i*4][bCol] = vb;
        }
        __syncthreads();

        #pragma unroll
        for (int kk = 0; kk < 16; ++kk) {
            float ar[8], br[8];
            #pragma unroll
            for (int i = 0; i < 8; ++i) ar[i] = As[kk][ty*8 + i];
            #pragma unroll
            for (int j = 0; j < 8; ++j) br[j] = Bs[kk][tx*8 + j];
            #pragma unroll
            for (int i = 0; i < 8; ++i)
                #pragma unroll
                for (int j = 0; j < 8; ++j)
                    acc[i*8 + j] = fmaf(ar[i], br[j], acc[i*8 + j]);
        }
        __syncthreads();
    }

    #pragma unroll
    for (int i = 0; i < 8; ++i) {
        const int row = bm + ty*8 + i;
        #pragma unroll
        for (int jj = 0; jj < 2; ++jj) {
            const int col = bn + tx*8 + jj*4;
            if (col < N) {
                float4 o;
                o.x = acc[i*8 + jj*4 + 0];
                o.y = acc[i*8 + jj*4 + 1];
                o.z = acc[i*8 + jj*4 + 2];
                o.w = acc[i*8 + jj*4 + 3];
                if (HAS_RES) {
                    float4 r = *(const float4*)(R + (size_t)row * N + col);
                    o.x += r.x; o.y += r.y; o.z += r.z; o.w += r.w;
                }
                *(float4*)(C + (size_t)row * N + col) = o;
            }
        }
    }
}

// ---------------- SwiGLU: f1 = silu(f1) * f2 ----------------
__global__ void swiglu_kernel(float* __restrict__ f1, const float* __restrict__ f2, int n4)
{
    int i = blockIdx.x * blockDim.x + threadIdx.x;
    if (i < n4) {
        float4 a = ((const float4*)f1)[i];
        float4 b = ((const float4*)f2)[i];
        a.x = a.x / (1.0f + __expf(-a.x)) * b.x;
        a.y = a.y / (1.0f + __expf(-a.y)) * b.y;
        a.z = a.z / (1.0f + __expf(-a.z)) * b.z;
        a.w = a.w / (1.0f + __expf(-a.w)) * b.w;
        ((float4*)f1)[i] = a;
    }
}

// ---------------- host launcher ----------------
extern "C" void kernel_launch(void* const* d_in, const int* in_sizes, int n_in,
                              void* d_out, int out_size)
{
    const float* x     = (const float*)d_in[0];
    const float* Wq    = (const float*)d_in[1];
    const float* Wk    = (const float*)d_in[2];
    const float* Wv    = (const float*)d_in[3];
    const float* Wg    = (const float*)d_in[4];
    const float* Wo    = (const float*)d_in[5];
    const float* w1    = (const float*)d_in[6];
    const float* w2    = (const float*)d_in[7];
    const float* w3    = (const float*)d_in[8];
    const float* gat   = (const float*)d_in[9];
    const float* gff   = (const float*)d_in[10];
    float* out = (float*)d_out;

    float *ph, *pq, *pk, *pv, *pa, *po, *px1, *pf1, *pf2, *pP, *pSs, *pAe;
    cudaGetSymbolAddress((void**)&ph,  g_h);
    cudaGetSymbolAddress((void**)&pq,  g_q);
    cudaGetSymbolAddress((void**)&pk,  g_k);
    cudaGetSymbolAddress((void**)&pv,  g_v);
    cudaGetSymbolAddress((void**)&pa,  g_a);
    cudaGetSymbolAddress((void**)&po,  g_o);
    cudaGetSymbolAddress((void**)&px1, g_x1);
    cudaGetSymbolAddress((void**)&pf1, g_f1);
    cudaGetSymbolAddress((void**)&pf2, g_f2);
    cudaGetSymbolAddress((void**)&pP,  g_P);
    cudaGetSymbolAddress((void**)&pSs, g_Ss);
    cudaGetSymbolAddress((void**)&pAe, g_Ae);

    static bool attr_done = false;
    if (!attr_done) {
        cudaFuncSetAttribute(chunk_output_kernel,
                             cudaFuncAttributeMaxDynamicSharedMemorySize,
                             4 * 64 * PAD * (int)sizeof(float));
        attr_done = true;
    }

    // 1) h = rmsnorm(x, g_attn)
    rmsnorm_kernel<<<BT, 256>>>(x, gat, ph);

    // 2) q,k,v,gate raw = h @ {Wq,Wk,Wv,Wg}
    {
        Ptrs4 p;
        p.B[0] = Wq; p.B[1] = Wk; p.B[2] = Wv; p.B[3] = Wg;
        p.C[0] = pq; p.C[1] = pk; p.C[2] = pv; p.C[3] = pa;
        dim3 grid(DM/128, BT/64, 4);
        sgemm_kernel<false><<<grid, 128>>>(ph, p, nullptr, BT, DM, DM);
    }

    // 3) l2norm(q), l2norm(k), log-sigmoid(gate) in place
    qknorm_kernel<<<BT, 256>>>(pq, pk, pa);

    // 4) chunked GLA
    chunk_summary_kernel<<<NBHC, 256>>>(pq, pk, pv, pa, pP, pAe);
    chunk_state_kernel  <<<32,   256>>>(pP, pAe, pSs);
    chunk_output_kernel <<<NBHC, 256, 4*64*PAD*(int)sizeof(float)>>>(pq, pk, pv, pSs, po);

    // 5) x1 = x + o @ Wo
    {
        Ptrs4 p;
        for (int i = 0; i < 4; ++i) { p.B[i] = Wo; p.C[i] = px1; }
        dim3 grid(DM/128, BT/64, 1);
        sgemm_kernel<true><<<grid, 128>>>(po, p, x, BT, DM, DM);
    }

    // 6) h = rmsnorm(x1, g_ffn)
    rmsnorm_kernel<<<BT, 256>>>(px1, gff, ph);

    // 7) f1 = h @ w1 ; f2 = h @ w2
    {
        Ptrs4 p;
        p.B[0] = w1; p.B[1] = w2; p.B[2] = w1; p.B[3] = w1;
        p.C[0] = pf1; p.C[1] = pf2; p.C[2] = pf1; p.C[3] = pf1;
        dim3 grid((DFF + 127)/128, BT/64, 2);
        sgemm_kernel<false><<<grid, 128>>>(ph, p, nullptr, BT, DFF, DM);
    }

    // 8) f1 = silu(f1) * f2
    {
        int n4 = (BT * DFF) / 4;
        swiglu_kernel<<<(n4 + 255)/256, 256>>>(pf1, pf2, n4);
    }

    // 9) out = x1 + f1 @ w3
    {
        Ptrs4 p;
        for (int i = 0; i < 4; ++i) { p.B[i] = w3; p.C[i] = out; }
        dim3 grid(DM/128, BT/64, 1);
        sgemm_kernel<true><<<grid, 128>>>(pf1, p, px1, BT, DM, DFF);
    }
}